// round 14
// baseline (speedup 1.0000x reference)
#include <cuda_runtime.h>
#include <cuda_bf16.h>
#include <cstdint>

#define EMBED  2048
#define FFN    8
#define GP     8        // tokens per stage
#define XSLOTS 3        // x ring triple-buffer (per-thread private cells)
#define QSLOTS 4        // q handoff ring depth (32 tokens of slack)

#define BAR_PROD     9
#define BAR_FULL(s)  (1 + (s))   // producer arrives, consumer syncs
#define BAR_EMPTY(s) (5 + (s))   // consumer arrives, producer syncs

// ---- packed f32x2 helpers ----
__device__ __forceinline__ unsigned long long fma2(unsigned long long a,
                                                   unsigned long long b,
                                                   unsigned long long c) {
    unsigned long long d;
    asm("fma.rn.f32x2 %0, %1, %2, %3;" : "=l"(d) : "l"(a), "l"(b), "l"(c));
    return d;
}
__device__ __forceinline__ unsigned long long pack2(float lo, float hi) {
    unsigned long long d;
    asm("mov.b64 %0, {%1, %2};" : "=l"(d) : "f"(lo), "f"(hi));
    return d;
}
__device__ __forceinline__ void unpack2(unsigned long long v, float& lo, float& hi) {
    asm("mov.b64 {%0, %1}, %2;" : "=f"(lo), "=f"(hi) : "l"(v));
}

__device__ __forceinline__ void bar_sync(int id, int cnt) {
    asm volatile("bar.sync %0, %1;" :: "r"(id), "r"(cnt) : "memory");
}
__device__ __forceinline__ void bar_arrive(int id, int cnt) {
    asm volatile("bar.arrive %0, %1;" :: "r"(id), "r"(cnt) : "memory");
}
__device__ __forceinline__ void cp16(uint32_t saddr, const void* gaddr) {
    asm volatile("cp.async.cg.shared.global [%0], [%1], 16;"
                 :: "r"(saddr), "l"(gaddr) : "memory");
}
__device__ __forceinline__ void cp_commit() {
    asm volatile("cp.async.commit_group;" ::: "memory");
}
__device__ __forceinline__ void cp_wait1() {
    asm volatile("cp.async.wait_group 1;" ::: "memory");
}

// smem layout (floats)
#define XRING_F  (XSLOTS * GP * EMBED)      // 49152 floats = 192 KB
#define SPART_F  (GP * 8 * FFN)             // 512
#define SQ_F     (QSLOTS * GP * FFN)        // 256
#define SMEM_F   (XRING_F + SPART_F + SQ_F + FFN)
#define SMEM_BYTES (SMEM_F * 4)

// ---------------------------------------------------------------------------
// Warp-specialized kernel: 1 block/SM, 512 threads.
//   warps 0-7  (tid 0-255):   producer — x -> gemm1 -> cos^2 -> s_q ring
//   warps 8-15 (tid 256-511): consumer — s_q ring -> gemm2 -> out
// x triple-buffered through cp.async: prefetch issued 2 stages ahead,
// wait_group 1 at stage top (slot cells are per-thread private, so slot
// recycling needs no barrier). q handed off through a 4-slot smem ring
// with named full/empty barriers.
// ---------------------------------------------------------------------------
__global__ __launch_bounds__(512, 1)
void qff_ws(const float* __restrict__ x,
            const float* __restrict__ W1,
            const float* __restrict__ b1,
            const float* __restrict__ W2,
            const float* __restrict__ b2,
            float* __restrict__ out,
            int ntok, int tpb)
{
    extern __shared__ float smem[];
    float* xring  = smem;
    float* s_part = smem + XRING_F;
    float* s_q    = smem + XRING_F + SPART_F;
    float* s_b1   = smem + XRING_F + SPART_F + SQ_F;

    const int tid   = threadIdx.x;
    const int start = blockIdx.x * tpb;
    const int end   = min(start + tpb, ntok);
    if (start >= end) return;                       // uniform for whole block
    const int nst = (end - start + GP - 1) / GP;

    if (tid < 256) {
        // ==================== PRODUCER (warps 0-7) ====================
        const int lane = tid & 31;
        const int warp = tid >> 5;
        if (tid < FFN) s_b1[tid] = b1[tid];

        // W1 slice register-resident: w1p[f][j] packs cols tid*8+2j, +2j+1
        unsigned long long w1p[FFN][4];
        #pragma unroll
        for (int f = 0; f < FFN; ++f) {
            const ulonglong2* p = reinterpret_cast<const ulonglong2*>(
                W1 + f * EMBED + tid * 8);
            ulonglong2 a = p[0], b = p[1];
            w1p[f][0] = a.x; w1p[f][1] = a.y; w1p[f][2] = b.x; w1p[f][3] = b.y;
        }

        const uint32_t xr = (uint32_t)__cvta_generic_to_shared(xring) + tid * 32;

        // Prologue: prefetch stages 0 and 1 (slots 0, 1), one group each.
        #pragma unroll
        for (int ps = 0; ps < 2; ++ps) {
            #pragma unroll
            for (int g = 0; g < GP; ++g) {
                const int t = start + ps * GP + g;
                if (t < end) {
                    const uint32_t dst = xr + (uint32_t)((ps * GP + g) * EMBED) * 4u;
                    const float* src = x + (size_t)t * EMBED + tid * 8;
                    cp16(dst, src);
                    cp16(dst + 16, src + 4);
                }
            }
            cp_commit();
        }

        int xs = 0;                      // slot of current stage (st % 3)
        for (int st = 0; st < nst; ++st) {
            const int qs = st & (QSLOTS - 1);
            const int t0 = start + st * GP;

            cp_wait1();                 // stage st's group done (st+1 in flight)
            bar_sync(BAR_PROD, 256);    // finalize(st-1) done -> s_part reusable

            // Prefetch stage st+2 into slot (st+2)%3. That slot's last reader
            // was this thread itself at stage st-1 (program order) -> safe.
            {
                const int pst  = st + 2;
                const int pt0  = start + pst * GP;
                int slot = xs + 2; if (slot >= XSLOTS) slot -= XSLOTS;
                #pragma unroll
                for (int g = 0; g < GP; ++g) {
                    const int t = pt0 + g;
                    if (t < end) {
                        const uint32_t dst = xr + (uint32_t)((slot * GP + g) * EMBED) * 4u;
                        const float* src = x + (size_t)t * EMBED + tid * 8;
                        cp16(dst, src);
                        cp16(dst + 16, src + 4);
                    }
                }
                cp_commit();            // commit even if empty (wait math)
            }

            // Compute GP tokens: LDS x, 32 fma2, fold to vst[g].
            // (Out-of-range tokens compute junk; finalize guards the write.)
            float vst[GP];
            #pragma unroll
            for (int g = 0; g < GP; ++g) {
                const ulonglong2* p = reinterpret_cast<const ulonglong2*>(
                    xring + (xs * GP + g) * EMBED + tid * 8);
                ulonglong2 a = p[0], b = p[1];
                unsigned long long xv[4] = {a.x, a.y, b.x, b.y};

                unsigned long long a2[FFN];
                #pragma unroll
                for (int f = 0; f < FFN; ++f) a2[f] = 0ull;
                #pragma unroll
                for (int j = 0; j < 4; ++j) {
                    #pragma unroll
                    for (int f = 0; f < FFN; ++f)
                        a2[f] = fma2(xv[j], w1p[f][j], a2[f]);
                }
                float acc[FFN];
                #pragma unroll
                for (int f = 0; f < FFN; ++f) {
                    float lo, hi; unpack2(a2[f], lo, hi);
                    acc[f] = lo + hi;
                }
                // transpose-reduce rounds xor1, xor2, xor4
                float v4[4];
                {
                    const bool hi = lane & 1;
                    #pragma unroll
                    for (int k = 0; k < 4; ++k) {
                        float keep = hi ? acc[k + 4] : acc[k];
                        float send = hi ? acc[k]     : acc[k + 4];
                        v4[k] = keep + __shfl_xor_sync(0xffffffffu, send, 1);
                    }
                }
                float v2[2];
                {
                    const bool hi = lane & 2;
                    #pragma unroll
                    for (int k = 0; k < 2; ++k) {
                        float keep = hi ? v4[k + 2] : v4[k];
                        float send = hi ? v4[k]     : v4[k + 2];
                        v2[k] = keep + __shfl_xor_sync(0xffffffffu, send, 2);
                    }
                }
                {
                    const bool hi = lane & 4;
                    float keep = hi ? v2[1] : v2[0];
                    float send = hi ? v2[0] : v2[1];
                    vst[g] = keep + __shfl_xor_sync(0xffffffffu, send, 4);
                }
            }

            // Finish warp reduction, stash per-warp partials.
            #pragma unroll
            for (int g = 0; g < GP; ++g) {
                float v = vst[g];
                v += __shfl_xor_sync(0xffffffffu, v, 8);
                v += __shfl_xor_sync(0xffffffffu, v, 16);
                if (lane < 8) {
                    const int f = ((lane & 1) << 2) | (lane & 2) | ((lane >> 2) & 1);
                    s_part[(g * 8 + warp) * FFN + f] = v;
                }
            }

            // q slot qs free (consumer arrived) + orders s_part for finalize.
            bar_sync(BAR_EMPTY(qs), 512);

            // Finalize: warp g finalizes token g (lane = feature).
            if (lane < FFN) {
                const int g = warp;
                const int t = t0 + g;
                if (t < end) {
                    float sum = s_b1[lane];
                    #pragma unroll
                    for (int w = 0; w < 8; ++w)
                        sum += s_part[(g * 8 + w) * FFN + lane];
                    sum = fmaxf(sum, 0.0f);
                    float c = __cosf(sum);
                    s_q[(qs * GP + g) * FFN + lane] = c * c;
                }
            }
            bar_arrive(BAR_FULL(qs), 512);

            if (++xs == XSLOTS) xs = 0;
        }
    } else {
        // ==================== CONSUMER (warps 8-15) ====================
        const int ct = tid - 256;

        // W2 slice + b2 register-resident (packed pairs).
        unsigned long long w2p[4][FFN];
        unsigned long long b2p[4];
        #pragma unroll
        for (int p = 0; p < 4; ++p) {
            const int e0 = ct * 8 + 2 * p;
            const float4* r0 = reinterpret_cast<const float4*>(W2 + (size_t)e0 * FFN);
            const float4* r1 = reinterpret_cast<const float4*>(W2 + (size_t)(e0 + 1) * FFN);
            float4 a0 = r0[0], a1 = r0[1];
            float4 c0 = r1[0], c1 = r1[1];
            w2p[p][0] = pack2(a0.x, c0.x); w2p[p][1] = pack2(a0.y, c0.y);
            w2p[p][2] = pack2(a0.z, c0.z); w2p[p][3] = pack2(a0.w, c0.w);
            w2p[p][4] = pack2(a1.x, c1.x); w2p[p][5] = pack2(a1.y, c1.y);
            w2p[p][6] = pack2(a1.z, c1.z); w2p[p][7] = pack2(a1.w, c1.w);
            b2p[p] = pack2(b2[e0], b2[e0 + 1]);
        }

        // Prime all empty barriers so producer's first QSLOTS waits pass.
        #pragma unroll
        for (int s = 0; s < QSLOTS; ++s) bar_arrive(BAR_EMPTY(s), 512);

        for (int st = 0; st < nst; ++st) {
            const int qs = st & (QSLOTS - 1);
            const int t0 = start + st * GP;

            bar_sync(BAR_FULL(qs), 512);   // q slot ready

            #pragma unroll
            for (int g = 0; g < GP; ++g) {
                const int t = t0 + g;
                if (t >= end) break;
                const float4* qp = reinterpret_cast<const float4*>(
                    s_q + (qs * GP + g) * FFN);
                float4 qa = qp[0], qb = qp[1];
                float qf[FFN] = {qa.x, qa.y, qa.z, qa.w, qb.x, qb.y, qb.z, qb.w};

                unsigned long long o2[4];
                #pragma unroll
                for (int p = 0; p < 4; ++p) o2[p] = b2p[p];
                #pragma unroll
                for (int f = 0; f < FFN; ++f) {
                    const unsigned long long qd = pack2(qf[f], qf[f]);
                    #pragma unroll
                    for (int p = 0; p < 4; ++p)
                        o2[p] = fma2(w2p[p][f], qd, o2[p]);
                }

                ulonglong2* o4 = reinterpret_cast<ulonglong2*>(
                    out + (size_t)t * EMBED + ct * 8);
                ulonglong2 s0; s0.x = o2[0]; s0.y = o2[1];
                ulonglong2 s1; s1.x = o2[2]; s1.y = o2[3];
                o4[0] = s0;
                o4[1] = s1;
            }

            bar_arrive(BAR_EMPTY(qs), 512);  // slot free for producer
        }
    }
}

// ---------------------------------------------------------------------------
// Launch: inputs in metadata order: x, W1, b1, W2, b2. Output float [N, EMBED].
// ---------------------------------------------------------------------------
extern "C" void kernel_launch(void* const* d_in, const int* in_sizes, int n_in,
                              void* d_out, int out_size)
{
    const float* x  = (const float*)d_in[0];
    const float* W1 = (const float*)d_in[1];
    const float* b1 = (const float*)d_in[2];
    const float* W2 = (const float*)d_in[3];
    const float* b2 = (const float*)d_in[4];
    float* out = (float*)d_out;

    const int ntok = in_sizes[0] / EMBED;

    int dev = 0;
    cudaGetDevice(&dev);
    int sms = 148;
    cudaDeviceGetAttribute(&sms, cudaDevAttrMultiProcessorCount, dev);

    static bool attr_done = false;
    if (!attr_done) {
        cudaFuncSetAttribute(qff_ws, cudaFuncAttributeMaxDynamicSharedMemorySize,
                             SMEM_BYTES);
        attr_done = true;
    }

    const int tpb = (ntok + sms - 1) / sms;

    qff_ws<<<sms, 512, SMEM_BYTES>>>(x, W1, b1, W2, b2, out, ntok, tpb);
}

// round 15
// speedup vs baseline: 1.0649x; 1.0649x over previous
#include <cuda_runtime.h>
#include <cuda_bf16.h>
#include <cstdint>

#define EMBED  2048
#define FFN    8
#define GP     8        // tokens per stage
#define XSLOTS 2        // x ring double-buffer (per-thread private cells)
#define QSLOTS 4        // q handoff ring depth (32 tokens of slack)

#define BAR_PROD     9
#define BAR_FULL(s)  (1 + (s))   // producer arrives, consumer syncs
#define BAR_EMPTY(s) (5 + (s))   // consumer arrives, producer syncs

// ---- packed f32x2 helpers ----
__device__ __forceinline__ unsigned long long fma2(unsigned long long a,
                                                   unsigned long long b,
                                                   unsigned long long c) {
    unsigned long long d;
    asm("fma.rn.f32x2 %0, %1, %2, %3;" : "=l"(d) : "l"(a), "l"(b), "l"(c));
    return d;
}
__device__ __forceinline__ unsigned long long pack2(float lo, float hi) {
    unsigned long long d;
    asm("mov.b64 %0, {%1, %2};" : "=l"(d) : "f"(lo), "f"(hi));
    return d;
}
__device__ __forceinline__ void unpack2(unsigned long long v, float& lo, float& hi) {
    asm("mov.b64 {%0, %1}, %2;" : "=f"(lo), "=f"(hi) : "l"(v));
}

__device__ __forceinline__ void bar_sync(int id, int cnt) {
    asm volatile("bar.sync %0, %1;" :: "r"(id), "r"(cnt) : "memory");
}
__device__ __forceinline__ void bar_arrive(int id, int cnt) {
    asm volatile("bar.arrive %0, %1;" :: "r"(id), "r"(cnt) : "memory");
}
__device__ __forceinline__ void cp16(uint32_t saddr, const void* gaddr) {
    asm volatile("cp.async.cg.shared.global [%0], [%1], 16;"
                 :: "r"(saddr), "l"(gaddr) : "memory");
}
__device__ __forceinline__ void cp_commit() {
    asm volatile("cp.async.commit_group;" ::: "memory");
}
__device__ __forceinline__ void cp_wait0() {
    asm volatile("cp.async.wait_group 0;" ::: "memory");
}

// smem layout (floats)
#define XRING_F  (XSLOTS * GP * EMBED)      // 32768 floats = 128 KB
#define SPART_F  (GP * 8 * FFN)             // 512
#define SQ_F     (QSLOTS * GP * FFN)        // 256
#define SMEM_F   (XRING_F + SPART_F + SQ_F + FFN)
#define SMEM_BYTES (SMEM_F * 4)

// ---------------------------------------------------------------------------
// Warp-specialized kernel: 1 block/SM, 512 threads.
//   warps 0-7  (tid 0-255):   producer — x -> gemm1 -> cos^2 -> s_q ring
//   warps 8-15 (tid 256-511): consumer — s_q ring -> gemm2 -> out
// x double-buffered through cp.async (slot cells are per-thread private:
// no barrier needed for recycling, wait_group 0 alone orders them).
// q handed off through a 4-slot smem ring with named full/empty barriers.
// ---------------------------------------------------------------------------
__global__ __launch_bounds__(512, 1)
void qff_ws(const float* __restrict__ x,
            const float* __restrict__ W1,
            const float* __restrict__ b1,
            const float* __restrict__ W2,
            const float* __restrict__ b2,
            float* __restrict__ out,
            int ntok, int tpb)
{
    extern __shared__ float smem[];
    float* xring  = smem;
    float* s_part = smem + XRING_F;
    float* s_q    = smem + XRING_F + SPART_F;
    float* s_b1   = smem + XRING_F + SPART_F + SQ_F;

    const int tid   = threadIdx.x;
    const int start = blockIdx.x * tpb;
    const int end   = min(start + tpb, ntok);
    if (start >= end) return;                       // uniform for whole block
    const int nst = (end - start + GP - 1) / GP;

    if (tid < 256) {
        // ==================== PRODUCER (warps 0-7) ====================
        const int lane = tid & 31;
        const int warp = tid >> 5;
        if (tid < FFN) s_b1[tid] = b1[tid];

        // W1 slice register-resident: w1p[f][j] packs cols tid*8+2j, +2j+1
        unsigned long long w1p[FFN][4];
        #pragma unroll
        for (int f = 0; f < FFN; ++f) {
            const ulonglong2* p = reinterpret_cast<const ulonglong2*>(
                W1 + f * EMBED + tid * 8);
            ulonglong2 a = p[0], b = p[1];
            w1p[f][0] = a.x; w1p[f][1] = a.y; w1p[f][2] = b.x; w1p[f][3] = b.y;
        }

        // This thread's byte address of its 32B cell within a token row.
        const uint32_t xr = (uint32_t)__cvta_generic_to_shared(xring) + tid * 32;

        // Prologue: prefetch stage 0 into slot 0.
        #pragma unroll
        for (int g = 0; g < GP; ++g) {
            const int t = start + g;
            if (t < end) {
                const uint32_t dst = xr + (uint32_t)(g * EMBED) * 4u;
                const float* src = x + (size_t)t * EMBED + tid * 8;
                cp16(dst, src);
                cp16(dst + 16, src + 4);
            }
        }
        cp_commit();

        for (int st = 0; st < nst; ++st) {
            const int xs = st & (XSLOTS - 1);
            const int qs = st & (QSLOTS - 1);
            const int t0 = start + st * GP;

            cp_wait0();                 // stage st's x ready (private cells)

            // Prefetch stage st+1 into the other slot BEFORE the barrier:
            // that slot's last reader was this thread itself in iteration
            // st-1 (program order) -> no barrier required, and issuing the
            // loads first lets them overlap the barrier wait.
            {
                const int pt0  = start + (st + 1) * GP;
                const int slot = (st + 1) & (XSLOTS - 1);
                #pragma unroll
                for (int g = 0; g < GP; ++g) {
                    const int t = pt0 + g;
                    if (t < end) {
                        const uint32_t dst = xr + (uint32_t)((slot * GP + g) * EMBED) * 4u;
                        const float* src = x + (size_t)t * EMBED + tid * 8;
                        cp16(dst, src);
                        cp16(dst + 16, src + 4);
                    }
                }
                cp_commit();            // commit even if empty (wait math)
            }

            bar_sync(BAR_PROD, 256);    // finalize(st-1) done -> s_part reusable

            // Compute GP tokens: LDS x, 32 fma2, fold to vst[g].
            float vst[GP];
            #pragma unroll
            for (int g = 0; g < GP; ++g) {
                const ulonglong2* p = reinterpret_cast<const ulonglong2*>(
                    xring + (xs * GP + g) * EMBED + tid * 8);
                ulonglong2 a = p[0], b = p[1];
                unsigned long long xv[4] = {a.x, a.y, b.x, b.y};

                unsigned long long a2[FFN];
                #pragma unroll
                for (int f = 0; f < FFN; ++f) a2[f] = 0ull;
                #pragma unroll
                for (int j = 0; j < 4; ++j) {
                    #pragma unroll
                    for (int f = 0; f < FFN; ++f)
                        a2[f] = fma2(xv[j], w1p[f][j], a2[f]);
                }
                float acc[FFN];
                #pragma unroll
                for (int f = 0; f < FFN; ++f) {
                    float lo, hi; unpack2(a2[f], lo, hi);
                    acc[f] = lo + hi;
                }
                // transpose-reduce rounds xor1, xor2, xor4
                float v4[4];
                {
                    const bool hi = lane & 1;
                    #pragma unroll
                    for (int k = 0; k < 4; ++k) {
                        float keep = hi ? acc[k + 4] : acc[k];
                        float send = hi ? acc[k]     : acc[k + 4];
                        v4[k] = keep + __shfl_xor_sync(0xffffffffu, send, 1);
                    }
                }
                float v2[2];
                {
                    const bool hi = lane & 2;
                    #pragma unroll
                    for (int k = 0; k < 2; ++k) {
                        float keep = hi ? v4[k + 2] : v4[k];
                        float send = hi ? v4[k]     : v4[k + 2];
                        v2[k] = keep + __shfl_xor_sync(0xffffffffu, send, 2);
                    }
                }
                {
                    const bool hi = lane & 4;
                    float keep = hi ? v2[1] : v2[0];
                    float send = hi ? v2[0] : v2[1];
                    vst[g] = keep + __shfl_xor_sync(0xffffffffu, send, 4);
                }
            }

            // Finish warp reduction, stash per-warp partials.
            #pragma unroll
            for (int g = 0; g < GP; ++g) {
                float v = vst[g];
                v += __shfl_xor_sync(0xffffffffu, v, 8);
                v += __shfl_xor_sync(0xffffffffu, v, 16);
                if (lane < 8) {
                    const int f = ((lane & 1) << 2) | (lane & 2) | ((lane >> 2) & 1);
                    s_part[(g * 8 + warp) * FFN + f] = v;
                }
            }

            // q slot qs free (consumer arrived) + orders s_part for finalize.
            bar_sync(BAR_EMPTY(qs), 512);

            // Finalize: warp g finalizes token g (lane = feature).
            if (lane < FFN) {
                const int g = warp;
                const int t = t0 + g;
                if (t < end) {
                    float sum = s_b1[lane];
                    #pragma unroll
                    for (int w = 0; w < 8; ++w)
                        sum += s_part[(g * 8 + w) * FFN + lane];
                    sum = fmaxf(sum, 0.0f);
                    float c = __cosf(sum);
                    s_q[(qs * GP + g) * FFN + lane] = c * c;
                }
            }
            bar_arrive(BAR_FULL(qs), 512);
        }
    } else {
        // ==================== CONSUMER (warps 8-15) ====================
        const int ct = tid - 256;

        // W2 slice + b2 register-resident (packed pairs).
        unsigned long long w2p[4][FFN];
        unsigned long long b2p[4];
        #pragma unroll
        for (int p = 0; p < 4; ++p) {
            const int e0 = ct * 8 + 2 * p;
            const float4* r0 = reinterpret_cast<const float4*>(W2 + (size_t)e0 * FFN);
            const float4* r1 = reinterpret_cast<const float4*>(W2 + (size_t)(e0 + 1) * FFN);
            float4 a0 = r0[0], a1 = r0[1];
            float4 c0 = r1[0], c1 = r1[1];
            w2p[p][0] = pack2(a0.x, c0.x); w2p[p][1] = pack2(a0.y, c0.y);
            w2p[p][2] = pack2(a0.z, c0.z); w2p[p][3] = pack2(a0.w, c0.w);
            w2p[p][4] = pack2(a1.x, c1.x); w2p[p][5] = pack2(a1.y, c1.y);
            w2p[p][6] = pack2(a1.z, c1.z); w2p[p][7] = pack2(a1.w, c1.w);
            b2p[p] = pack2(b2[e0], b2[e0 + 1]);
        }

        // Prime all empty barriers so producer's first QSLOTS waits pass.
        #pragma unroll
        for (int s = 0; s < QSLOTS; ++s) bar_arrive(BAR_EMPTY(s), 512);

        for (int st = 0; st < nst; ++st) {
            const int qs = st & (QSLOTS - 1);
            const int t0 = start + st * GP;

            bar_sync(BAR_FULL(qs), 512);   // q slot ready

            #pragma unroll
            for (int g = 0; g < GP; ++g) {
                const int t = t0 + g;
                if (t >= end) break;
                const float4* qp = reinterpret_cast<const float4*>(
                    s_q + (qs * GP + g) * FFN);
                float4 qa = qp[0], qb = qp[1];
                float qf[FFN] = {qa.x, qa.y, qa.z, qa.w, qb.x, qb.y, qb.z, qb.w};

                unsigned long long o2[4];
                #pragma unroll
                for (int p = 0; p < 4; ++p) o2[p] = b2p[p];
                #pragma unroll
                for (int f = 0; f < FFN; ++f) {
                    const unsigned long long qd = pack2(qf[f], qf[f]);
                    #pragma unroll
                    for (int p = 0; p < 4; ++p)
                        o2[p] = fma2(w2p[p][f], qd, o2[p]);
                }

                ulonglong2* o4 = reinterpret_cast<ulonglong2*>(
                    out + (size_t)t * EMBED + ct * 8);
                ulonglong2 s0; s0.x = o2[0]; s0.y = o2[1];
                ulonglong2 s1; s1.x = o2[2]; s1.y = o2[3];
                o4[0] = s0;
                o4[1] = s1;
            }

            bar_arrive(BAR_EMPTY(qs), 512);  // slot free for producer
        }
    }
}

// ---------------------------------------------------------------------------
// Launch: inputs in metadata order: x, W1, b1, W2, b2. Output float [N, EMBED].
// ---------------------------------------------------------------------------
extern "C" void kernel_launch(void* const* d_in, const int* in_sizes, int n_in,
                              void* d_out, int out_size)
{
    const float* x  = (const float*)d_in[0];
    const float* W1 = (const float*)d_in[1];
    const float* b1 = (const float*)d_in[2];
    const float* W2 = (const float*)d_in[3];
    const float* b2 = (const float*)d_in[4];
    float* out = (float*)d_out;

    const int ntok = in_sizes[0] / EMBED;

    int dev = 0;
    cudaGetDevice(&dev);
    int sms = 148;
    cudaDeviceGetAttribute(&sms, cudaDevAttrMultiProcessorCount, dev);

    static bool attr_done = false;
    if (!attr_done) {
        cudaFuncSetAttribute(qff_ws, cudaFuncAttributeMaxDynamicSharedMemorySize,
                             SMEM_BYTES);
        attr_done = true;
    }

    const int tpb = (ntok + sms - 1) / sms;

    qff_ws<<<sms, 512, SMEM_BYTES>>>(x, W1, b1, W2, b2, out, ntok, tpb);
}

// round 16
// speedup vs baseline: 1.1467x; 1.0768x over previous
#include <cuda_runtime.h>
#include <cuda_bf16.h>
#include <cstdint>

#define EMBED  2048
#define FFN    8
#define GP     8        // tokens per stage
#define XSLOTS 2        // x ring double-buffer
#define QSLOTS 4        // q handoff ring depth (32 tokens of slack)

#define BAR_PROD     9
#define BAR_FULL(s)  (1 + (s))   // producer arrives, consumer syncs
#define BAR_EMPTY(s) (5 + (s))   // consumer arrives, producer syncs

// ---- packed f32x2 helpers ----
__device__ __forceinline__ unsigned long long fma2(unsigned long long a,
                                                   unsigned long long b,
                                                   unsigned long long c) {
    unsigned long long d;
    asm("fma.rn.f32x2 %0, %1, %2, %3;" : "=l"(d) : "l"(a), "l"(b), "l"(c));
    return d;
}
__device__ __forceinline__ unsigned long long pack2(float lo, float hi) {
    unsigned long long d;
    asm("mov.b64 %0, {%1, %2};" : "=l"(d) : "f"(lo), "f"(hi));
    return d;
}
__device__ __forceinline__ void unpack2(unsigned long long v, float& lo, float& hi) {
    asm("mov.b64 {%0, %1}, %2;" : "=f"(lo), "=f"(hi) : "l"(v));
}

__device__ __forceinline__ void bar_sync(int id, int cnt) {
    asm volatile("bar.sync %0, %1;" :: "r"(id), "r"(cnt) : "memory");
}
__device__ __forceinline__ void bar_arrive(int id, int cnt) {
    asm volatile("bar.arrive %0, %1;" :: "r"(id), "r"(cnt) : "memory");
}

// ---- mbarrier + TMA bulk helpers ----
__device__ __forceinline__ void mbar_init(uint32_t mbar, uint32_t cnt) {
    asm volatile("mbarrier.init.shared.b64 [%0], %1;" :: "r"(mbar), "r"(cnt) : "memory");
}
__device__ __forceinline__ void mbar_expect_tx(uint32_t mbar, uint32_t bytes) {
    asm volatile("mbarrier.arrive.expect_tx.shared.b64 _, [%0], %1;"
                 :: "r"(mbar), "r"(bytes) : "memory");
}
__device__ __forceinline__ void mbar_wait(uint32_t mbar, uint32_t phase) {
    asm volatile(
        "{\n\t"
        ".reg .pred P;\n\t"
        "WAIT_%=:\n\t"
        "mbarrier.try_wait.parity.acquire.cta.shared::cta.b64 P, [%0], %1, 0x989680;\n\t"
        "@P bra.uni DONE_%=;\n\t"
        "bra.uni WAIT_%=;\n\t"
        "DONE_%=:\n\t"
        "}"
        :: "r"(mbar), "r"(phase) : "memory");
}
__device__ __forceinline__ void bulk_load(uint32_t sdst, const void* gsrc,
                                          uint32_t bytes, uint32_t mbar) {
    asm volatile(
        "cp.async.bulk.shared::cluster.global.mbarrier::complete_tx::bytes "
        "[%0], [%1], %2, [%3];"
        :: "r"(sdst), "l"(gsrc), "r"(bytes), "r"(mbar) : "memory");
}
__device__ __forceinline__ void fence_proxy_async_cta() {
    asm volatile("fence.proxy.async.shared::cta;" ::: "memory");
}

// smem layout (floats)
#define XRING_F  (XSLOTS * GP * EMBED)      // 32768 floats = 128 KB
#define SPART_F  (GP * 8 * FFN)             // 512
#define SQ_F     (QSLOTS * GP * FFN)        // 256
#define SMEM_CORE_F (XRING_F + SPART_F + SQ_F + FFN)
// mbarriers: 16-byte aligned region after the float area, 2 x 8 bytes
#define MBAR_OFF_B  (((SMEM_CORE_F * 4) + 15) & ~15)
#define SMEM_BYTES  (MBAR_OFF_B + 32)

// ---------------------------------------------------------------------------
// Warp-specialized kernel: 1 block/SM, 512 threads.
//   warps 0-7  (tid 0-255):   producer — x -> gemm1 -> cos^2 -> s_q ring
//   warps 8-15 (tid 256-511): consumer — s_q ring -> gemm2 -> out
// x double-buffered via ONE cp.async.bulk (TMA) per 64 KB stage, tracked by
// per-slot mbarriers (phase = (st>>1)&1). Slot recycling ordering comes from
// the BAR_EMPTY 512-thread sync of the prior stage (program order on the
// issuing thread). q handed off through a 4-slot ring w/ named barriers.
// ---------------------------------------------------------------------------
__global__ __launch_bounds__(512, 1)
void qff_ws(const float* __restrict__ x,
            const float* __restrict__ W1,
            const float* __restrict__ b1,
            const float* __restrict__ W2,
            const float* __restrict__ b2,
            float* __restrict__ out,
            int ntok, int tpb)
{
    extern __shared__ float smem[];
    float* xring  = smem;
    float* s_part = smem + XRING_F;
    float* s_q    = smem + XRING_F + SPART_F;
    float* s_b1   = smem + XRING_F + SPART_F + SQ_F;

    const int tid   = threadIdx.x;
    const int start = blockIdx.x * tpb;
    const int end   = min(start + tpb, ntok);
    if (start >= end) return;                       // uniform for whole block
    const int nst = (end - start + GP - 1) / GP;

    if (tid < 256) {
        // ==================== PRODUCER (warps 0-7) ====================
        const int lane = tid & 31;
        const int warp = tid >> 5;
        if (tid < FFN) s_b1[tid] = b1[tid];

        // W1 slice register-resident: w1p[f][j] packs cols tid*8+2j, +2j+1
        unsigned long long w1p[FFN][4];
        #pragma unroll
        for (int f = 0; f < FFN; ++f) {
            const ulonglong2* p = reinterpret_cast<const ulonglong2*>(
                W1 + f * EMBED + tid * 8);
            ulonglong2 a = p[0], b = p[1];
            w1p[f][0] = a.x; w1p[f][1] = a.y; w1p[f][2] = b.x; w1p[f][3] = b.y;
        }

        const uint32_t sbase = (uint32_t)__cvta_generic_to_shared(smem);
        const uint32_t xbase = sbase;                    // xring at offset 0
        const uint32_t mbar  = sbase + MBAR_OFF_B;       // 2 mbarriers

        // Init mbarriers, publish to producer warps, issue stage-0 bulk.
        if (tid == 0) {
            mbar_init(mbar + 0, 1);
            mbar_init(mbar + 8, 1);
            fence_proxy_async_cta();
        }
        bar_sync(BAR_PROD, 256);
        if (tid == 0) {
            const uint32_t bytes = (uint32_t)min(GP, end - start) * EMBED * 4u;
            mbar_expect_tx(mbar + 0, bytes);
            bulk_load(xbase, x + (size_t)start * EMBED, bytes, mbar + 0);
        }

        for (int st = 0; st < nst; ++st) {
            const int xs = st & (XSLOTS - 1);
            const int qs = st & (QSLOTS - 1);
            const int t0 = start + st * GP;
            const uint32_t ph = (uint32_t)(st >> 1) & 1u;

            mbar_wait(mbar + xs * 8, ph);   // stage st's x tile ready

            // Issue stage st+1 bulk into the other slot. That slot's reads
            // finished before BAR_EMPTY(st-1) (512-thread sync), which this
            // thread passed in program order -> safe without extra barrier.
            {
                const int pt0 = start + (st + 1) * GP;
                if (pt0 < end && tid == 0) {
                    const int  slot  = (st + 1) & (XSLOTS - 1);
                    const uint32_t bytes = (uint32_t)min(GP, end - pt0) * EMBED * 4u;
                    mbar_expect_tx(mbar + slot * 8, bytes);
                    bulk_load(xbase + (uint32_t)slot * GP * EMBED * 4u,
                              x + (size_t)pt0 * EMBED, bytes, mbar + slot * 8);
                }
            }

            bar_sync(BAR_PROD, 256);    // finalize(st-1) done -> s_part reusable

            // Compute GP tokens: LDS x, 32 fma2, fold to vst[g].
            // (Tail tokens read stale smem junk; finalize guards the write.)
            float vst[GP];
            #pragma unroll
            for (int g = 0; g < GP; ++g) {
                const ulonglong2* p = reinterpret_cast<const ulonglong2*>(
                    xring + (xs * GP + g) * EMBED + tid * 8);
                ulonglong2 a = p[0], b = p[1];
                unsigned long long xv[4] = {a.x, a.y, b.x, b.y};

                unsigned long long a2[FFN];
                #pragma unroll
                for (int f = 0; f < FFN; ++f) a2[f] = 0ull;
                #pragma unroll
                for (int j = 0; j < 4; ++j) {
                    #pragma unroll
                    for (int f = 0; f < FFN; ++f)
                        a2[f] = fma2(xv[j], w1p[f][j], a2[f]);
                }
                float acc[FFN];
                #pragma unroll
                for (int f = 0; f < FFN; ++f) {
                    float lo, hi; unpack2(a2[f], lo, hi);
                    acc[f] = lo + hi;
                }
                // transpose-reduce rounds xor1, xor2, xor4
                float v4[4];
                {
                    const bool hi = lane & 1;
                    #pragma unroll
                    for (int k = 0; k < 4; ++k) {
                        float keep = hi ? acc[k + 4] : acc[k];
                        float send = hi ? acc[k]     : acc[k + 4];
                        v4[k] = keep + __shfl_xor_sync(0xffffffffu, send, 1);
                    }
                }
                float v2[2];
                {
                    const bool hi = lane & 2;
                    #pragma unroll
                    for (int k = 0; k < 2; ++k) {
                        float keep = hi ? v4[k + 2] : v4[k];
                        float send = hi ? v4[k]     : v4[k + 2];
                        v2[k] = keep + __shfl_xor_sync(0xffffffffu, send, 2);
                    }
                }
                {
                    const bool hi = lane & 4;
                    float keep = hi ? v2[1] : v2[0];
                    float send = hi ? v2[0] : v2[1];
                    vst[g] = keep + __shfl_xor_sync(0xffffffffu, send, 4);
                }
            }

            // Finish warp reduction, stash per-warp partials.
            #pragma unroll
            for (int g = 0; g < GP; ++g) {
                float v = vst[g];
                v += __shfl_xor_sync(0xffffffffu, v, 8);
                v += __shfl_xor_sync(0xffffffffu, v, 16);
                if (lane < 8) {
                    const int f = ((lane & 1) << 2) | (lane & 2) | ((lane >> 2) & 1);
                    s_part[(g * 8 + warp) * FFN + f] = v;
                }
            }

            // q slot qs free (consumer arrived) + orders s_part for finalize.
            bar_sync(BAR_EMPTY(qs), 512);

            // Finalize: warp g finalizes token g (lane = feature).
            if (lane < FFN) {
                const int g = warp;
                const int t = t0 + g;
                if (t < end) {
                    float sum = s_b1[lane];
                    #pragma unroll
                    for (int w = 0; w < 8; ++w)
                        sum += s_part[(g * 8 + w) * FFN + lane];
                    sum = fmaxf(sum, 0.0f);
                    float c = __cosf(sum);
                    s_q[(qs * GP + g) * FFN + lane] = c * c;
                }
            }
            bar_arrive(BAR_FULL(qs), 512);
        }
    } else {
        // ==================== CONSUMER (warps 8-15) ====================
        const int ct = tid - 256;

        // W2 slice + b2 register-resident (packed pairs).
        unsigned long long w2p[4][FFN];
        unsigned long long b2p[4];
        #pragma unroll
        for (int p = 0; p < 4; ++p) {
            const int e0 = ct * 8 + 2 * p;
            const float4* r0 = reinterpret_cast<const float4*>(W2 + (size_t)e0 * FFN);
            const float4* r1 = reinterpret_cast<const float4*>(W2 + (size_t)(e0 + 1) * FFN);
            float4 a0 = r0[0], a1 = r0[1];
            float4 c0 = r1[0], c1 = r1[1];
            w2p[p][0] = pack2(a0.x, c0.x); w2p[p][1] = pack2(a0.y, c0.y);
            w2p[p][2] = pack2(a0.z, c0.z); w2p[p][3] = pack2(a0.w, c0.w);
            w2p[p][4] = pack2(a1.x, c1.x); w2p[p][5] = pack2(a1.y, c1.y);
            w2p[p][6] = pack2(a1.z, c1.z); w2p[p][7] = pack2(a1.w, c1.w);
            b2p[p] = pack2(b2[e0], b2[e0 + 1]);
        }

        // Prime all empty barriers so producer's first QSLOTS waits pass.
        #pragma unroll
        for (int s = 0; s < QSLOTS; ++s) bar_arrive(BAR_EMPTY(s), 512);

        for (int st = 0; st < nst; ++st) {
            const int qs = st & (QSLOTS - 1);
            const int t0 = start + st * GP;

            bar_sync(BAR_FULL(qs), 512);   // q slot ready

            #pragma unroll
            for (int g = 0; g < GP; ++g) {
                const int t = t0 + g;
                if (t >= end) break;
                const float4* qp = reinterpret_cast<const float4*>(
                    s_q + (qs * GP + g) * FFN);
                float4 qa = qp[0], qb = qp[1];
                float qf[FFN] = {qa.x, qa.y, qa.z, qa.w, qb.x, qb.y, qb.z, qb.w};

                unsigned long long o2[4];
                #pragma unroll
                for (int p = 0; p < 4; ++p) o2[p] = b2p[p];
                #pragma unroll
                for (int f = 0; f < FFN; ++f) {
                    const unsigned long long qd = pack2(qf[f], qf[f]);
                    #pragma unroll
                    for (int p = 0; p < 4; ++p)
                        o2[p] = fma2(w2p[p][f], qd, o2[p]);
                }

                ulonglong2* o4 = reinterpret_cast<ulonglong2*>(
                    out + (size_t)t * EMBED + ct * 8);
                ulonglong2 s0; s0.x = o2[0]; s0.y = o2[1];
                ulonglong2 s1; s1.x = o2[2]; s1.y = o2[3];
                o4[0] = s0;
                o4[1] = s1;
            }

            bar_arrive(BAR_EMPTY(qs), 512);  // slot free for producer
        }
    }
}

// ---------------------------------------------------------------------------
// Launch: inputs in metadata order: x, W1, b1, W2, b2. Output float [N, EMBED].
// ---------------------------------------------------------------------------
extern "C" void kernel_launch(void* const* d_in, const int* in_sizes, int n_in,
                              void* d_out, int out_size)
{
    const float* x  = (const float*)d_in[0];
    const float* W1 = (const float*)d_in[1];
    const float* b1 = (const float*)d_in[2];
    const float* W2 = (const float*)d_in[3];
    const float* b2 = (const float*)d_in[4];
    float* out = (float*)d_out;

    const int ntok = in_sizes[0] / EMBED;

    int dev = 0;
    cudaGetDevice(&dev);
    int sms = 148;
    cudaDeviceGetAttribute(&sms, cudaDevAttrMultiProcessorCount, dev);

    static bool attr_done = false;
    if (!attr_done) {
        cudaFuncSetAttribute(qff_ws, cudaFuncAttributeMaxDynamicSharedMemorySize,
                             SMEM_BYTES);
        attr_done = true;
    }

    const int tpb = (ntok + sms - 1) / sms;

    qff_ws<<<sms, 512, SMEM_BYTES>>>(x, W1, b1, W2, b2, out, ntok, tpb);
}